// round 11
// baseline (speedup 1.0000x reference)
#include <cuda_runtime.h>
#include <cuda_bf16.h>
#include <cstddef>
#include <cstdint>

#define TT   1024
#define BB   64
#define FF   512          // feature dim (== 2H, both layers share K=512)
#define HH   256
#define GXN  1280         // 5*H
#define NBLK 128          // recurrence blocks: 2 dirs * 64 slices

// ---------------- scratch (device globals; no runtime allocation) ------------
__device__ float g_y  [(size_t)TT*BB*FF];        // layer-0 output / layer-1 input (fp32)
__device__ float g_fin[(size_t)TT*BB*FF];        // layer-1 output
__device__ float g_gx [2][(size_t)TT*BB*GXN];    // per-dir input-gate projections
__device__ float g_px [2][(size_t)TT*BB*HH];     // per-dir highway projections
__device__ float g_h  [2][2][HH*BB];             // [parity][dir][k][b] hidden exchange
__device__ unsigned g_bar;

// bf16 split operands
__device__ __nv_bfloat16 g_xh[(size_t)TT*BB*FF], g_xl[(size_t)TT*BB*FF];
__device__ __nv_bfloat16 g_yh[(size_t)TT*BB*FF], g_yl[(size_t)TT*BB*FF];
__device__ __nv_bfloat16 g_wxh[2*2*FF*GXN], g_wxl[2*2*FF*GXN];
__device__ __nv_bfloat16 g_wph[2*2*FF*HH],  g_wpl[2*2*FF*HH];

// ---------------- helpers ----------------------------------------------------
__device__ __forceinline__ void split1(float x, __nv_bfloat16& h, __nv_bfloat16& l) {
    h = __float2bfloat16(x);
    l = __float2bfloat16(x - __bfloat162float(h));
}

// transpose+split: features [b][t][512] fp32 -> xh/xl [t][b][512] bf16
__global__ void k_tin(const float* __restrict__ feat,
                      __nv_bfloat16* __restrict__ xh, __nv_bfloat16* __restrict__ xl) {
    int row = blockIdx.x;               // b*T + t
    int b = row >> 10, t = row & 1023;
    float4 v = ((const float4*)(feat + (size_t)row * FF))[threadIdx.x];
    size_t drow = ((size_t)t * BB + b) * FF + threadIdx.x * 4;
    __nv_bfloat16 h4[4], l4[4];
    split1(v.x, h4[0], l4[0]); split1(v.y, h4[1], l4[1]);
    split1(v.z, h4[2], l4[2]); split1(v.w, h4[3], l4[3]);
    *(uint2*)(xh + drow) = *(uint2*)h4;
    *(uint2*)(xl + drow) = *(uint2*)l4;
}

// generic fp32 -> bf16 hi/lo split (n4 = element count / 4)
__global__ void k_split(const float* __restrict__ in,
                        __nv_bfloat16* __restrict__ hi, __nv_bfloat16* __restrict__ lo, int n4) {
    int i = blockIdx.x * blockDim.x + threadIdx.x;
    if (i >= n4) return;
    float4 v = ((const float4*)in)[i];
    __nv_bfloat16 h4[4], l4[4];
    split1(v.x, h4[0], l4[0]); split1(v.y, h4[1], l4[1]);
    split1(v.z, h4[2], l4[2]); split1(v.w, h4[3], l4[3]);
    *(uint2*)(hi + (size_t)i * 4) = *(uint2*)h4;
    *(uint2*)(lo + (size_t)i * 4) = *(uint2*)l4;
}

// transpose: fin [t][b][512] -> out [b][t][512]
__global__ void k_tout(const float* __restrict__ fin, float* __restrict__ out) {
    int row = blockIdx.x;               // t*B + b
    int t = row >> 6, b = row & 63;
    const float4* s = (const float4*)(fin + (size_t)row * FF);
    float4* d = (float4*)(out + (((size_t)b << 10) + t) * FF);
    for (int i = threadIdx.x; i < FF / 4; i += blockDim.x) d[i] = s[i];
}

// ---------------- PTX wrappers -----------------------------------------------
__device__ __forceinline__ void ldsm_x4(uint32_t* r, uint32_t a) {
    asm volatile("ldmatrix.sync.aligned.m8n8.x4.shared.b16 {%0,%1,%2,%3}, [%4];"
        : "=r"(r[0]), "=r"(r[1]), "=r"(r[2]), "=r"(r[3]) : "r"(a));
}
__device__ __forceinline__ void ldsm_x4_t(uint32_t* r, uint32_t a) {
    asm volatile("ldmatrix.sync.aligned.m8n8.x4.trans.shared.b16 {%0,%1,%2,%3}, [%4];"
        : "=r"(r[0]), "=r"(r[1]), "=r"(r[2]), "=r"(r[3]) : "r"(a));
}
__device__ __forceinline__ void mma_bf16(float* c, const uint32_t* a, const uint32_t* b) {
    asm volatile("mma.sync.aligned.m16n8k16.row.col.f32.bf16.bf16.f32 "
        "{%0,%1,%2,%3},{%4,%5,%6,%7},{%8,%9},{%0,%1,%2,%3};"
        : "+f"(c[0]), "+f"(c[1]), "+f"(c[2]), "+f"(c[3])
        : "r"(a[0]), "r"(a[1]), "r"(a[2]), "r"(a[3]), "r"(b[0]), "r"(b[1]));
}
__device__ __forceinline__ void cp16(uint32_t s, const void* g) {
    asm volatile("cp.async.cg.shared.global [%0], [%1], 16;" :: "r"(s), "l"(g));
}
#define CP_COMMIT asm volatile("cp.async.commit_group;")
#define CP_WAIT1  asm volatile("cp.async.wait_group 1;")
#define CP_WAIT0  asm volatile("cp.async.wait_group 0;")

// packed fp32x2 FMA: d = a*b + d (per 32-bit lane) -> SASS FFMA2
#define FMA_F32X2(d, a, b) \
    asm("fma.rn.f32x2 %0, %1, %2, %0;" : "+l"(d) : "l"(a), "l"(b))

__device__ __forceinline__ float2 ull2f2(unsigned long long u) {
    float2 f;
    asm("mov.b64 {%0, %1}, %2;" : "=f"(f.x), "=f"(f.y) : "l"(u));
    return f;
}
__device__ __forceinline__ unsigned long long f2ull(float a, float b) {
    unsigned long long u;
    asm("mov.b64 %0, {%1, %2};" : "=l"(u) : "f"(a), "f"(b));
    return u;
}

// ---------------- tensor-core split-bf16 GEMM --------------------------------
// C[M,N] = Ahi@Bhi + Ahi@Blo + Alo@Bhi + bias.  Tiles 128x128x32, 256 threads.
#define STG_A 10240               // 128 rows * 80B pitch
#define STG_B 8192                // 32 rows * 256B, XOR-swizzled
#define STG_SZ (2*STG_A + 2*STG_B)
#define SMEM_MMA (2*STG_SZ)       // double-buffered: 73728 B

__global__ __launch_bounds__(256)
void k_mma(const __nv_bfloat16* __restrict__ Ah, const __nv_bfloat16* __restrict__ Al,
           const __nv_bfloat16* __restrict__ Bh, const __nv_bfloat16* __restrict__ Bl,
           const float* __restrict__ bias, float* __restrict__ C, int N, int K) {
    extern __shared__ char smem[];
    uint32_t su = (uint32_t)__cvta_generic_to_shared(smem);
    int tid = threadIdx.x, lane = tid & 31, wid = tid >> 5;
    int mw = wid & 3, nw = wid >> 2;          // 4x2 warp grid
    int m0 = blockIdx.y * 128, n0 = blockIdx.x * 128;

    float acc[2][8][4];
#pragma unroll
    for (int mi = 0; mi < 2; mi++)
#pragma unroll
        for (int j = 0; j < 8; j++)
#pragma unroll
            for (int q = 0; q < 4; q++) acc[mi][j][q] = 0.f;

    auto load_stage = [&](int st, int k0) {
        uint32_t sa = su + st * STG_SZ;
#pragma unroll
        for (int hl = 0; hl < 2; hl++) {
            const __nv_bfloat16* Ap = hl ? Al : Ah;
            uint32_t sb = sa + hl * STG_A;
#pragma unroll
            for (int rep = 0; rep < 2; rep++) {
                int idx = tid + rep * 256;          // 0..511
                int r = idx >> 2, c = idx & 3;
                cp16(sb + r * 80 + c * 16, Ap + (size_t)(m0 + r) * K + k0 + c * 8);
            }
        }
#pragma unroll
        for (int hl = 0; hl < 2; hl++) {
            const __nv_bfloat16* Bp = hl ? Bl : Bh;
            uint32_t sb = sa + 2 * STG_A + hl * STG_B;
#pragma unroll
            for (int rep = 0; rep < 2; rep++) {
                int idx = tid + rep * 256;
                int k = idx >> 4, c = idx & 15;
                cp16(sb + k * 256 + ((c ^ (k & 7)) * 16),
                     Bp + (size_t)(k0 + k) * N + n0 + c * 8);
            }
        }
    };

    int NIT = K >> 5;                             // 16 for K=512
    load_stage(0, 0);
    CP_COMMIT;

    for (int it = 0; it < NIT; it++) {
        if (it + 1 < NIT) { load_stage((it + 1) & 1, (it + 1) * 32); CP_COMMIT; CP_WAIT1; }
        else              { CP_WAIT0; }
        __syncthreads();

        uint32_t sa = su + (it & 1) * STG_SZ;
#pragma unroll
        for (int kk = 0; kk < 2; kk++) {
            uint32_t ah[2][4], al[2][4];
            int arow_c = kk * 2 + (lane >> 4);
            int arow_r = (lane & 15);
#pragma unroll
            for (int mi = 0; mi < 2; mi++) {
                uint32_t ad = sa + (mw * 32 + mi * 16 + arow_r) * 80 + arow_c * 16;
                ldsm_x4(ah[mi], ad);
                ldsm_x4(al[mi], ad + STG_A);
            }
#pragma unroll
            for (int jp = 0; jp < 4; jp++) {
                int krow = kk * 16 + (lane & 15);
                int cch  = nw * 8 + jp * 2 + (lane >> 4);
                uint32_t bd = sa + 2 * STG_A + krow * 256 + ((cch ^ (krow & 7)) * 16);
                uint32_t bh[4], bl[4];
                ldsm_x4_t(bh, bd);
                ldsm_x4_t(bl, bd + STG_B);
#pragma unroll
                for (int jj = 0; jj < 2; jj++) {
#pragma unroll
                    for (int mi = 0; mi < 2; mi++) {
                        float* a4 = acc[mi][jp * 2 + jj];
                        mma_bf16(a4, ah[mi], &bh[jj * 2]);  // Ahi @ Bhi
                        mma_bf16(a4, ah[mi], &bl[jj * 2]);  // Ahi @ Blo
                        mma_bf16(a4, al[mi], &bh[jj * 2]);  // Alo @ Bhi
                    }
                }
            }
        }
        __syncthreads();
    }

#pragma unroll
    for (int mi = 0; mi < 2; mi++) {
#pragma unroll
        for (int j = 0; j < 8; j++) {
            int row = m0 + mw * 32 + mi * 16 + (lane >> 2);
            int col = n0 + nw * 64 + j * 8 + (lane & 3) * 2;
            float b0 = bias[col], b1 = bias[col + 1];
            float2 v0 = {acc[mi][j][0] + b0, acc[mi][j][1] + b1};
            float2 v1 = {acc[mi][j][2] + b0, acc[mi][j][3] + b1};
            *(float2*)(C + (size_t)row * N + col)       = v0;
            *(float2*)(C + (size_t)(row + 8) * N + col) = v1;
        }
    }
}

// ---------------- reset barrier + h buffers (before each recurrence) ---------
__global__ void k_reset() {
    int i = blockIdx.x * blockDim.x + threadIdx.x;
    if (i == 0) g_bar = 0u;
    float* gh = &g_h[0][0][0];
    if (i < 2 * 2 * HH * BB) gh[i] = 0.f;
}

// ---------------- persistent bidirectional highway-LSTM scan -----------------
// grid = 128 blocks: blockIdx.x = d + 2*j.  Inner product now runs on packed
// fp32x2 FFMA2: Wh is pre-duplicated into smem as (w,w) b64 pairs, h staged as
// b64 pairs, 10 FFMA2 per k per thread (4 batches x 5 gates).
#define REC_SMEM (256*20*8 + 256*64*4)   // 40960 w-pairs + 65536 h stage = 104 KB

__device__ __forceinline__ float sigf(float x) { return 1.f / (1.f + expf(-x)); }

__global__ __launch_bounds__(128, 1)
void k_rec(const float* __restrict__ Wh_l,   // [2][256][1280] (this layer)
           const float* __restrict__ bh_l,   // [2][1280]
           const float* __restrict__ gx0, const float* __restrict__ gx1,
           const float* __restrict__ px0, const float* __restrict__ px1,
           float* __restrict__ outbuf) {     // [t][b][512] (fwd|bwd concat)
    extern __shared__ char smc[];
    unsigned long long* w_s = (unsigned long long*)smc;   // [256*20] duplicated pairs
    float* h_s = (float*)(smc + 256 * 20 * 8);            // [256 k][64 b]
    float* red = h_s;                                     // reused for kh reduction

    int tid = threadIdx.x;
    int d  = blockIdx.x & 1;
    int j  = blockIdx.x >> 1;
    int c  = tid & 3;
    int bq = (tid >> 2) & 15;
    int kh = tid >> 6;
    int col = j * 4 + c;
    int b0  = bq * 4;
    int be  = b0 + kh * 2;           // epilogue batches: be, be+1

    const float* Wh_d = Wh_l + (size_t)d * HH * GXN;
    const float* gx = d ? gx1 : gx0;
    const float* px = d ? px1 : px0;

    for (int idx = tid; idx < 256 * 20; idx += 128) {
        int k = idx / 20, gc = idx % 20;
        int g = gc >> 2, cc = gc & 3;
        float v = Wh_d[(size_t)k * GXN + g * HH + j * 4 + cc];
        w_s[idx] = f2ull(v, v);
    }
    float bh5[5];
#pragma unroll
    for (int g = 0; g < 5; g++) bh5[g] = bh_l[(size_t)d * GXN + g * HH + col];

    float cs0 = 0.f, cs1 = 0.f;
    __syncthreads();

    for (int s = 0; s < TT; s++) {
        int t = d ? (TT - 1 - s) : s;

        size_t r0 = ((size_t)t * BB + be) * GXN;
        float gxa[5], gxb[5];
#pragma unroll
        for (int g = 0; g < 5; g++) {
            gxa[g] = __ldg(gx + r0 + g * HH + col);
            gxb[g] = __ldg(gx + r0 + GXN + g * HH + col);
        }
        float pxa = __ldg(px + ((size_t)t * BB + be) * HH + col);
        float pxb = __ldg(px + ((size_t)t * BB + be + 1) * HH + col);

        // stage h_prev (written by all slice-blocks last step) via L2
        {
            const float4* src = (const float4*)&g_h[s & 1][d][0];
            float4* dst = (float4*)h_s;
#pragma unroll
            for (int i = 0; i < 32; i++) dst[tid + i * 128] = __ldcg(&src[tid + i * 128]);
        }
        __syncthreads();

        // packed inner product: acc2[g][p] accumulates batches (b0+2p, b0+2p+1)
        unsigned long long acc2[5][2];
#pragma unroll
        for (int g = 0; g < 5; g++) { acc2[g][0] = 0ull; acc2[g][1] = 0ull; }
        int kb = kh * 128;
#pragma unroll 8
        for (int k = 0; k < 128; k++) {
            const unsigned long long* hp =
                (const unsigned long long*)&h_s[(kb + k) * BB + b0];
            unsigned long long h0 = hp[0], h1 = hp[1];
            const unsigned long long* wp = w_s + (size_t)(kb + k) * 20 + c;
#pragma unroll
            for (int g = 0; g < 5; g++) {
                unsigned long long w2 = wp[g * 4];
                FMA_F32X2(acc2[g][0], h0, w2);
                FMA_F32X2(acc2[g][1], h1, w2);
            }
        }
        __syncthreads();                       // h_s no longer needed -> red

        float2 A0[5], A1[5];
#pragma unroll
        for (int g = 0; g < 5; g++) { A0[g] = ull2f2(acc2[g][0]); A1[g] = ull2f2(acc2[g][1]); }

        // exchange the 2 components the partner kh-thread finalizes
        int slot = (bq * 4 + c) * 10;
        float* myred = red + kh * 640 + slot;
        if (kh == 0) {
#pragma unroll
            for (int g = 0; g < 5; g++) { myred[g * 2] = A1[g].x; myred[g * 2 + 1] = A1[g].y; }
        } else {
#pragma unroll
            for (int g = 0; g < 5; g++) { myred[g * 2] = A0[g].x; myred[g * 2 + 1] = A0[g].y; }
        }
        __syncthreads();
        const float* pr = red + (1 - kh) * 640 + slot;
        float za[5], zb[5];
        if (kh == 0) {
#pragma unroll
            for (int g = 0; g < 5; g++) { za[g] = A0[g].x + pr[g * 2]; zb[g] = A0[g].y + pr[g * 2 + 1]; }
        } else {
#pragma unroll
            for (int g = 0; g < 5; g++) { za[g] = A1[g].x + pr[g * 2]; zb[g] = A1[g].y + pr[g * 2 + 1]; }
        }

        // gates: z split order = i, o, f, u, r
        {
            float zi = za[0] + gxa[0] + bh5[0];
            float zo = za[1] + gxa[1] + bh5[1];
            float zf = za[2] + gxa[2] + bh5[2];
            float zu = za[3] + gxa[3] + bh5[3];
            float zr = za[4] + gxa[4] + bh5[4];
            cs0 = sigf(zi) * tanhf(zu) + sigf(zf) * cs0;
            float hhv = sigf(zo) * tanhf(cs0);
            float rg  = sigf(zr);
            float hf  = rg * hhv + (1.f - rg) * pxa;
            __stcg(&g_h[(s + 1) & 1][d][col * BB + be], hf);
            outbuf[((size_t)t * BB + be) * FF + d * HH + col] = hf;
        }
        {
            float zi = zb[0] + gxb[0] + bh5[0];
            float zo = zb[1] + gxb[1] + bh5[1];
            float zf = zb[2] + gxb[2] + bh5[2];
            float zu = zb[3] + gxb[3] + bh5[3];
            float zr = zb[4] + gxb[4] + bh5[4];
            cs1 = sigf(zi) * tanhf(zu) + sigf(zf) * cs1;
            float hhv = sigf(zo) * tanhf(cs1);
            float rg  = sigf(zr);
            float hf  = rg * hhv + (1.f - rg) * pxb;
            __stcg(&g_h[(s + 1) & 1][d][col * BB + be + 1], hf);
            outbuf[((size_t)t * BB + be + 1) * FF + d * HH + col] = hf;
        }

        // grid barrier: make h stores visible, arrive, spin on monotonic count
        __threadfence();
        __syncthreads();
        if (tid == 0) {
            atomicAdd(&g_bar, 1u);
            unsigned target = (unsigned)(s + 1) * NBLK;
            volatile unsigned* vb = &g_bar;
            while (*vb < target) __nanosleep(40);
        }
        __syncthreads();
    }
}

// ---------------------------- host driver ------------------------------------
extern "C" void kernel_launch(void* const* d_in, const int* in_sizes, int n_in,
                              void* d_out, int out_size) {
    (void)in_sizes; (void)n_in; (void)out_size;
    const float* feat = (const float*)d_in[0];
    const float* Wx   = (const float*)d_in[1];  // [2][2][512][1280]
    const float* bx   = (const float*)d_in[2];  // [2][2][1280]
    const float* Wh   = (const float*)d_in[3];  // [2][2][256][1280]
    const float* bh   = (const float*)d_in[4];  // [2][2][1280]
    const float* Wp   = (const float*)d_in[5];  // [2][2][512][256]
    const float* bp   = (const float*)d_in[6];  // [2][2][256]
    float* out = (float*)d_out;

    float *p_y, *p_f, *p_gx, *p_px;
    __nv_bfloat16 *p_xh, *p_xl, *p_yh, *p_yl, *p_wxh, *p_wxl, *p_wph, *p_wpl;
    cudaGetSymbolAddress((void**)&p_y,   g_y);
    cudaGetSymbolAddress((void**)&p_f,   g_fin);
    cudaGetSymbolAddress((void**)&p_gx,  g_gx);
    cudaGetSymbolAddress((void**)&p_px,  g_px);
    cudaGetSymbolAddress((void**)&p_xh,  g_xh);
    cudaGetSymbolAddress((void**)&p_xl,  g_xl);
    cudaGetSymbolAddress((void**)&p_yh,  g_yh);
    cudaGetSymbolAddress((void**)&p_yl,  g_yl);
    cudaGetSymbolAddress((void**)&p_wxh, g_wxh);
    cudaGetSymbolAddress((void**)&p_wxl, g_wxl);
    cudaGetSymbolAddress((void**)&p_wph, g_wph);
    cudaGetSymbolAddress((void**)&p_wpl, g_wpl);

    cudaFuncSetAttribute(k_rec, cudaFuncAttributeMaxDynamicSharedMemorySize, REC_SMEM);
    cudaFuncSetAttribute(k_mma, cudaFuncAttributeMaxDynamicSharedMemorySize, SMEM_MMA);

    const size_t GXSZ = (size_t)TT * BB * GXN;
    const size_t PXSZ = (size_t)TT * BB * HH;

    k_tin<<<TT * BB, 128>>>(feat, p_xh, p_xl);
    k_split<<<(2 * 2 * FF * GXN / 4 + 255) / 256, 256>>>(Wx, p_wxh, p_wxl, 2 * 2 * FF * GXN / 4);
    k_split<<<(2 * 2 * FF * HH  / 4 + 255) / 256, 256>>>(Wp, p_wph, p_wpl, 2 * 2 * FF * HH / 4);

    for (int l = 0; l < 2; l++) {
        const __nv_bfloat16* Ah = l ? p_yh : p_xh;
        const __nv_bfloat16* Al = l ? p_yl : p_xl;
        float* OUT = l ? p_f : p_y;
        for (int dd = 0; dd < 2; dd++) {
            int w = l * 2 + dd;
            k_mma<<<dim3(GXN / 128, (TT * BB) / 128), 256, SMEM_MMA>>>(
                Ah, Al, p_wxh + (size_t)w * FF * GXN, p_wxl + (size_t)w * FF * GXN,
                bx + (size_t)w * GXN, p_gx + dd * GXSZ, GXN, FF);
            k_mma<<<dim3(HH / 128, (TT * BB) / 128), 256, SMEM_MMA>>>(
                Ah, Al, p_wph + (size_t)w * FF * HH, p_wpl + (size_t)w * FF * HH,
                bp + (size_t)w * HH, p_px + dd * PXSZ, HH, FF);
        }
        k_reset<<<256, 256>>>();
        k_rec<<<NBLK, 128, REC_SMEM>>>(
            Wh + (size_t)l * 2 * HH * GXN, bh + (size_t)l * 2 * GXN,
            p_gx, p_gx + GXSZ, p_px, p_px + PXSZ, OUT);
        if (l == 0)
            k_split<<<(TT * BB * FF / 4) / 256, 256>>>(p_y, p_yh, p_yl, TT * BB * FF / 4);
    }

    k_tout<<<TT * BB, 128>>>(p_f, out);
}

// round 12
// speedup vs baseline: 1.0876x; 1.0876x over previous
#include <cuda_runtime.h>
#include <cuda_bf16.h>
#include <cstddef>
#include <cstdint>

#define TT   1024
#define BB   64
#define FF   512          // feature dim (== 2H, both layers share K=512)
#define HH   256
#define GXN  1280         // 5*H
#define NBLK 128          // recurrence blocks: 2 dirs * 64 slices

// ---------------- scratch (device globals; no runtime allocation) ------------
__device__ float g_y  [(size_t)TT*BB*FF];        // layer-0 output / layer-1 input (fp32)
__device__ float g_fin[(size_t)TT*BB*FF];        // layer-1 output
__device__ float g_gx [2][(size_t)TT*BB*GXN];    // per-dir input-gate projections
__device__ float g_px [2][(size_t)TT*BB*HH];     // per-dir highway projections
__device__ float g_h  [2][2][HH*BB];             // [parity][dir][k][b] hidden exchange
__device__ unsigned g_bar;

// bf16 split operands
__device__ __nv_bfloat16 g_xh[(size_t)TT*BB*FF], g_xl[(size_t)TT*BB*FF];
__device__ __nv_bfloat16 g_yh[(size_t)TT*BB*FF], g_yl[(size_t)TT*BB*FF];
__device__ __nv_bfloat16 g_wxh[2*2*FF*GXN], g_wxl[2*2*FF*GXN];
__device__ __nv_bfloat16 g_wph[2*2*FF*HH],  g_wpl[2*2*FF*HH];

// ---------------- helpers ----------------------------------------------------
__device__ __forceinline__ void split1(float x, __nv_bfloat16& h, __nv_bfloat16& l) {
    h = __float2bfloat16(x);
    l = __float2bfloat16(x - __bfloat162float(h));
}

// transpose+split: features [b][t][512] fp32 -> xh/xl [t][b][512] bf16
__global__ void k_tin(const float* __restrict__ feat,
                      __nv_bfloat16* __restrict__ xh, __nv_bfloat16* __restrict__ xl) {
    int row = blockIdx.x;               // b*T + t
    int b = row >> 10, t = row & 1023;
    float4 v = ((const float4*)(feat + (size_t)row * FF))[threadIdx.x];
    size_t drow = ((size_t)t * BB + b) * FF + threadIdx.x * 4;
    __nv_bfloat16 h4[4], l4[4];
    split1(v.x, h4[0], l4[0]); split1(v.y, h4[1], l4[1]);
    split1(v.z, h4[2], l4[2]); split1(v.w, h4[3], l4[3]);
    *(uint2*)(xh + drow) = *(uint2*)h4;
    *(uint2*)(xl + drow) = *(uint2*)l4;
}

// generic fp32 -> bf16 hi/lo split (n4 = element count / 4)
__global__ void k_split(const float* __restrict__ in,
                        __nv_bfloat16* __restrict__ hi, __nv_bfloat16* __restrict__ lo, int n4) {
    int i = blockIdx.x * blockDim.x + threadIdx.x;
    if (i >= n4) return;
    float4 v = ((const float4*)in)[i];
    __nv_bfloat16 h4[4], l4[4];
    split1(v.x, h4[0], l4[0]); split1(v.y, h4[1], l4[1]);
    split1(v.z, h4[2], l4[2]); split1(v.w, h4[3], l4[3]);
    *(uint2*)(hi + (size_t)i * 4) = *(uint2*)h4;
    *(uint2*)(lo + (size_t)i * 4) = *(uint2*)l4;
}

// transpose: fin [t][b][512] -> out [b][t][512]
__global__ void k_tout(const float* __restrict__ fin, float* __restrict__ out) {
    int row = blockIdx.x;               // t*B + b
    int t = row >> 6, b = row & 63;
    const float4* s = (const float4*)(fin + (size_t)row * FF);
    float4* d = (float4*)(out + (((size_t)b << 10) + t) * FF);
    for (int i = threadIdx.x; i < FF / 4; i += blockDim.x) d[i] = s[i];
}

// ---------------- PTX wrappers -----------------------------------------------
__device__ __forceinline__ void ldsm_x4(uint32_t* r, uint32_t a) {
    asm volatile("ldmatrix.sync.aligned.m8n8.x4.shared.b16 {%0,%1,%2,%3}, [%4];"
        : "=r"(r[0]), "=r"(r[1]), "=r"(r[2]), "=r"(r[3]) : "r"(a));
}
__device__ __forceinline__ void ldsm_x4_t(uint32_t* r, uint32_t a) {
    asm volatile("ldmatrix.sync.aligned.m8n8.x4.trans.shared.b16 {%0,%1,%2,%3}, [%4];"
        : "=r"(r[0]), "=r"(r[1]), "=r"(r[2]), "=r"(r[3]) : "r"(a));
}
__device__ __forceinline__ void mma_bf16(float* c, const uint32_t* a, const uint32_t* b) {
    asm volatile("mma.sync.aligned.m16n8k16.row.col.f32.bf16.bf16.f32 "
        "{%0,%1,%2,%3},{%4,%5,%6,%7},{%8,%9},{%0,%1,%2,%3};"
        : "+f"(c[0]), "+f"(c[1]), "+f"(c[2]), "+f"(c[3])
        : "r"(a[0]), "r"(a[1]), "r"(a[2]), "r"(a[3]), "r"(b[0]), "r"(b[1]));
}
__device__ __forceinline__ void cp16(uint32_t s, const void* g) {
    asm volatile("cp.async.cg.shared.global [%0], [%1], 16;" :: "r"(s), "l"(g));
}
#define CP_COMMIT asm volatile("cp.async.commit_group;")
#define CP_WAIT1  asm volatile("cp.async.wait_group 1;")
#define CP_WAIT0  asm volatile("cp.async.wait_group 0;")

// ---------------- tensor-core split-bf16 GEMM --------------------------------
// C[M,N] = Ahi@Bhi + Ahi@Blo + Alo@Bhi + bias.  Tiles 128x128x32, 256 threads.
#define STG_A 10240               // 128 rows * 80B pitch
#define STG_B 8192                // 32 rows * 256B, XOR-swizzled
#define STG_SZ (2*STG_A + 2*STG_B)
#define SMEM_MMA (2*STG_SZ)       // double-buffered: 73728 B

__global__ __launch_bounds__(256)
void k_mma(const __nv_bfloat16* __restrict__ Ah, const __nv_bfloat16* __restrict__ Al,
           const __nv_bfloat16* __restrict__ Bh, const __nv_bfloat16* __restrict__ Bl,
           const float* __restrict__ bias, float* __restrict__ C, int N, int K) {
    extern __shared__ char smem[];
    uint32_t su = (uint32_t)__cvta_generic_to_shared(smem);
    int tid = threadIdx.x, lane = tid & 31, wid = tid >> 5;
    int mw = wid & 3, nw = wid >> 2;          // 4x2 warp grid
    int m0 = blockIdx.y * 128, n0 = blockIdx.x * 128;

    float acc[2][8][4];
#pragma unroll
    for (int mi = 0; mi < 2; mi++)
#pragma unroll
        for (int j = 0; j < 8; j++)
#pragma unroll
            for (int q = 0; q < 4; q++) acc[mi][j][q] = 0.f;

    auto load_stage = [&](int st, int k0) {
        uint32_t sa = su + st * STG_SZ;
#pragma unroll
        for (int hl = 0; hl < 2; hl++) {
            const __nv_bfloat16* Ap = hl ? Al : Ah;
            uint32_t sb = sa + hl * STG_A;
#pragma unroll
            for (int rep = 0; rep < 2; rep++) {
                int idx = tid + rep * 256;          // 0..511
                int r = idx >> 2, c = idx & 3;
                cp16(sb + r * 80 + c * 16, Ap + (size_t)(m0 + r) * K + k0 + c * 8);
            }
        }
#pragma unroll
        for (int hl = 0; hl < 2; hl++) {
            const __nv_bfloat16* Bp = hl ? Bl : Bh;
            uint32_t sb = sa + 2 * STG_A + hl * STG_B;
#pragma unroll
            for (int rep = 0; rep < 2; rep++) {
                int idx = tid + rep * 256;
                int k = idx >> 4, c = idx & 15;
                cp16(sb + k * 256 + ((c ^ (k & 7)) * 16),
                     Bp + (size_t)(k0 + k) * N + n0 + c * 8);
            }
        }
    };

    int NIT = K >> 5;                             // 16 for K=512
    load_stage(0, 0);
    CP_COMMIT;

    for (int it = 0; it < NIT; it++) {
        if (it + 1 < NIT) { load_stage((it + 1) & 1, (it + 1) * 32); CP_COMMIT; CP_WAIT1; }
        else              { CP_WAIT0; }
        __syncthreads();

        uint32_t sa = su + (it & 1) * STG_SZ;
#pragma unroll
        for (int kk = 0; kk < 2; kk++) {
            uint32_t ah[2][4], al[2][4];
            int arow_c = kk * 2 + (lane >> 4);
            int arow_r = (lane & 15);
#pragma unroll
            for (int mi = 0; mi < 2; mi++) {
                uint32_t ad = sa + (mw * 32 + mi * 16 + arow_r) * 80 + arow_c * 16;
                ldsm_x4(ah[mi], ad);
                ldsm_x4(al[mi], ad + STG_A);
            }
#pragma unroll
            for (int jp = 0; jp < 4; jp++) {
                int krow = kk * 16 + (lane & 15);
                int cch  = nw * 8 + jp * 2 + (lane >> 4);
                uint32_t bd = sa + 2 * STG_A + krow * 256 + ((cch ^ (krow & 7)) * 16);
                uint32_t bh[4], bl[4];
                ldsm_x4_t(bh, bd);
                ldsm_x4_t(bl, bd + STG_B);
#pragma unroll
                for (int jj = 0; jj < 2; jj++) {
#pragma unroll
                    for (int mi = 0; mi < 2; mi++) {
                        float* a4 = acc[mi][jp * 2 + jj];
                        mma_bf16(a4, ah[mi], &bh[jj * 2]);  // Ahi @ Bhi
                        mma_bf16(a4, ah[mi], &bl[jj * 2]);  // Ahi @ Blo
                        mma_bf16(a4, al[mi], &bh[jj * 2]);  // Alo @ Bhi
                    }
                }
            }
        }
        __syncthreads();
    }

#pragma unroll
    for (int mi = 0; mi < 2; mi++) {
#pragma unroll
        for (int j = 0; j < 8; j++) {
            int row = m0 + mw * 32 + mi * 16 + (lane >> 2);
            int col = n0 + nw * 64 + j * 8 + (lane & 3) * 2;
            float b0 = bias[col], b1 = bias[col + 1];
            float2 v0 = {acc[mi][j][0] + b0, acc[mi][j][1] + b1};
            float2 v1 = {acc[mi][j][2] + b0, acc[mi][j][3] + b1};
            *(float2*)(C + (size_t)row * N + col)       = v0;
            *(float2*)(C + (size_t)(row + 8) * N + col) = v1;
        }
    }
}

// ---------------- reset barrier + h buffers (before each recurrence) ---------
__global__ void k_reset() {
    int i = blockIdx.x * blockDim.x + threadIdx.x;
    if (i == 0) g_bar = 0u;
    float* gh = &g_h[0][0][0];
    if (i < 2 * 2 * HH * BB) gh[i] = 0.f;
}

// ---------------- persistent bidirectional highway-LSTM scan -----------------
// grid = 128 blocks: blockIdx.x = d + 2*j  (d: direction, j: 4-col slice 0..63)
// block = 256 threads (2 warps/SMSP for latency hiding):
//   c  = tid&3        column within the 4-col slice
//   bp = (tid>>2)&31  batch pair (batches 2bp, 2bp+1)
//   kh = tid>>7       k half (0: k 0..127, 1: k 128..255)
// Each thread: 5 gates x 2 batches over its k half; kh-partner exchange in
// smem; each thread finalizes gates for exactly one (col, batch) element.
#define REC_SMEM ((256*20 + 256*64) * 4)   // 84 KB

__device__ __forceinline__ float sigf(float x) { return 1.f / (1.f + expf(-x)); }

__global__ __launch_bounds__(256, 1)
void k_rec(const float* __restrict__ Wh_l,   // [2][256][1280] (this layer)
           const float* __restrict__ bh_l,   // [2][1280]
           const float* __restrict__ gx0, const float* __restrict__ gx1,
           const float* __restrict__ px0, const float* __restrict__ px1,
           float* __restrict__ outbuf) {     // [t][b][512] (fwd|bwd concat)
    extern __shared__ float sm[];
    float* w_s = sm;                 // [256][20] Wh slice (gate-interleaved)
    float* h_s = sm + 256 * 20;      // [256 k][64 b] staged h_prev
    float* red = h_s;                // reused post-k-loop for kh reduction (1280 floats)

    int tid = threadIdx.x;
    int d  = blockIdx.x & 1;
    int j  = blockIdx.x >> 1;
    int c  = tid & 3;
    int bp = (tid >> 2) & 31;
    int kh = tid >> 7;
    int col = j * 4 + c;
    int b0  = bp * 2;
    int be  = b0 + kh;               // the one batch this thread finalizes

    const float* Wh_d = Wh_l + (size_t)d * HH * GXN;
    const float* gx = d ? gx1 : gx0;
    const float* px = d ? px1 : px0;

    for (int idx = tid; idx < 256 * 20; idx += 256) {
        int k = idx / 20, gc = idx % 20;
        int g = gc >> 2, cc = gc & 3;
        w_s[idx] = Wh_d[(size_t)k * GXN + g * HH + j * 4 + cc];
    }
    float bh5[5];
#pragma unroll
    for (int g = 0; g < 5; g++) bh5[g] = bh_l[(size_t)d * GXN + g * HH + col];

    float cs = 0.f;                  // cell state for batch be
    __syncthreads();

    for (int s = 0; s < TT; s++) {
        int t = d ? (TT - 1 - s) : s;

        // prefetch gate inputs for this thread's batch (resolve during k-loop)
        size_t r0 = ((size_t)t * BB + be) * GXN;
        float gxa[5];
#pragma unroll
        for (int g = 0; g < 5; g++) gxa[g] = __ldg(gx + r0 + g * HH + col);
        float pxa = __ldg(px + ((size_t)t * BB + be) * HH + col);

        // stage h_prev (written by all slice-blocks last step) via L2
        {
            const float4* src = (const float4*)&g_h[s & 1][d][0];
            float4* dst = (float4*)h_s;
#pragma unroll
            for (int i = 0; i < 16; i++) dst[tid + i * 256] = __ldcg(&src[tid + i * 256]);
        }
        __syncthreads();

        float2 acc[5];
#pragma unroll
        for (int g = 0; g < 5; g++) acc[g] = make_float2(0.f, 0.f);
        int kb = kh * 128;
#pragma unroll 8
        for (int k = 0; k < 128; k++) {
            float2 hv = *(const float2*)&h_s[(kb + k) * BB + b0];
#pragma unroll
            for (int g = 0; g < 5; g++) {
                float w = w_s[(kb + k) * 20 + g * 4 + c];
                acc[g].x += hv.x * w;
                acc[g].y += hv.y * w;
            }
        }
        __syncthreads();                       // h_s no longer needed -> red

        // exchange: write the partial of the batch the kh-partner finalizes
        int base = (bp * 4 + c) * 2;
        float* my = red + (base + kh) * 5;
        if (kh == 0) {
#pragma unroll
            for (int g = 0; g < 5; g++) my[g] = acc[g].y;   // partial of batch b0+1
        } else {
#pragma unroll
            for (int g = 0; g < 5; g++) my[g] = acc[g].x;   // partial of batch b0
        }
        __syncthreads();
        const float* pr = red + (base + (1 - kh)) * 5;
        float z5[5];
        if (kh == 0) {
#pragma unroll
            for (int g = 0; g < 5; g++) z5[g] = acc[g].x + pr[g];
        } else {
#pragma unroll
            for (int g = 0; g < 5; g++) z5[g] = acc[g].y + pr[g];
        }

        // gates: z split order = i, o, f, u, r
        {
            float zi = z5[0] + gxa[0] + bh5[0];
            float zo = z5[1] + gxa[1] + bh5[1];
            float zf = z5[2] + gxa[2] + bh5[2];
            float zu = z5[3] + gxa[3] + bh5[3];
            float zr = z5[4] + gxa[4] + bh5[4];
            cs = sigf(zi) * tanhf(zu) + sigf(zf) * cs;
            float hhv = sigf(zo) * tanhf(cs);
            float rg  = sigf(zr);
            float hf  = rg * hhv + (1.f - rg) * pxa;
            __stcg(&g_h[(s + 1) & 1][d][col * BB + be], hf);
            outbuf[((size_t)t * BB + be) * FF + d * HH + col] = hf;
        }

        // grid barrier: make h stores visible, arrive, spin on monotonic count
        __threadfence();
        __syncthreads();
        if (tid == 0) {
            atomicAdd(&g_bar, 1u);
            unsigned target = (unsigned)(s + 1) * NBLK;
            volatile unsigned* vb = &g_bar;
            while (*vb < target) __nanosleep(40);
        }
        __syncthreads();
    }
}

// ---------------------------- host driver ------------------------------------
extern "C" void kernel_launch(void* const* d_in, const int* in_sizes, int n_in,
                              void* d_out, int out_size) {
    (void)in_sizes; (void)n_in; (void)out_size;
    const float* feat = (const float*)d_in[0];
    const float* Wx   = (const float*)d_in[1];  // [2][2][512][1280]
    const float* bx   = (const float*)d_in[2];  // [2][2][1280]
    const float* Wh   = (const float*)d_in[3];  // [2][2][256][1280]
    const float* bh   = (const float*)d_in[4];  // [2][2][1280]
    const float* Wp   = (const float*)d_in[5];  // [2][2][512][256]
    const float* bp   = (const float*)d_in[6];  // [2][2][256]
    float* out = (float*)d_out;

    float *p_y, *p_f, *p_gx, *p_px;
    __nv_bfloat16 *p_xh, *p_xl, *p_yh, *p_yl, *p_wxh, *p_wxl, *p_wph, *p_wpl;
    cudaGetSymbolAddress((void**)&p_y,   g_y);
    cudaGetSymbolAddress((void**)&p_f,   g_fin);
    cudaGetSymbolAddress((void**)&p_gx,  g_gx);
    cudaGetSymbolAddress((void**)&p_px,  g_px);
    cudaGetSymbolAddress((void**)&p_xh,  g_xh);
    cudaGetSymbolAddress((void**)&p_xl,  g_xl);
    cudaGetSymbolAddress((void**)&p_yh,  g_yh);
    cudaGetSymbolAddress((void**)&p_yl,  g_yl);
    cudaGetSymbolAddress((void**)&p_wxh, g_wxh);
    cudaGetSymbolAddress((void**)&p_wxl, g_wxl);
    cudaGetSymbolAddress((void**)&p_wph, g_wph);
    cudaGetSymbolAddress((void**)&p_wpl, g_wpl);

    cudaFuncSetAttribute(k_rec, cudaFuncAttributeMaxDynamicSharedMemorySize, REC_SMEM);
    cudaFuncSetAttribute(k_mma, cudaFuncAttributeMaxDynamicSharedMemorySize, SMEM_MMA);

    const size_t GXSZ = (size_t)TT * BB * GXN;
    const size_t PXSZ = (size_t)TT * BB * HH;

    k_tin<<<TT * BB, 128>>>(feat, p_xh, p_xl);
    k_split<<<(2 * 2 * FF * GXN / 4 + 255) / 256, 256>>>(Wx, p_wxh, p_wxl, 2 * 2 * FF * GXN / 4);
    k_split<<<(2 * 2 * FF * HH  / 4 + 255) / 256, 256>>>(Wp, p_wph, p_wpl, 2 * 2 * FF * HH / 4);

    for (int l = 0; l < 2; l++) {
        const __nv_bfloat16* Ah = l ? p_yh : p_xh;
        const __nv_bfloat16* Al = l ? p_yl : p_xl;
        float* OUT = l ? p_f : p_y;
        for (int dd = 0; dd < 2; dd++) {
            int w = l * 2 + dd;
            k_mma<<<dim3(GXN / 128, (TT * BB) / 128), 256, SMEM_MMA>>>(
                Ah, Al, p_wxh + (size_t)w * FF * GXN, p_wxl + (size_t)w * FF * GXN,
                bx + (size_t)w * GXN, p_gx + dd * GXSZ, GXN, FF);
            k_mma<<<dim3(HH / 128, (TT * BB) / 128), 256, SMEM_MMA>>>(
                Ah, Al, p_wph + (size_t)w * FF * HH, p_wpl + (size_t)w * FF * HH,
                bp + (size_t)w * HH, p_px + dd * PXSZ, HH, FF);
        }
        k_reset<<<256, 256>>>();
        k_rec<<<NBLK, 256, REC_SMEM>>>(
            Wh + (size_t)l * 2 * HH * GXN, bh + (size_t)l * 2 * GXN,
            p_gx, p_gx + GXSZ, p_px, p_px + PXSZ, OUT);
        if (l == 0)
            k_split<<<(TT * BB * FF / 4) / 256, 256>>>(p_y, p_yh, p_yl, TT * BB * FF / 4);
    }

    k_tout<<<TT * BB, 128>>>(p_f, out);
}

// round 13
// speedup vs baseline: 1.1287x; 1.0378x over previous
#include <cuda_runtime.h>
#include <cuda_bf16.h>
#include <cstddef>
#include <cstdint>

#define TT   1024
#define BB   64
#define FF   512          // feature dim (== 2H, both layers share K=512)
#define HH   256
#define GXN  1280         // 5*H
#define NBLK 128          // recurrence blocks: 2 dirs * 64 slices

// ---------------- scratch (device globals; no runtime allocation) ------------
__device__ float g_y  [(size_t)TT*BB*FF];        // layer-0 output / layer-1 input (fp32)
__device__ float g_fin[(size_t)TT*BB*FF];        // layer-1 output
__device__ float g_gx [2][(size_t)TT*BB*GXN];    // per-dir input-gate projections
__device__ float g_px [2][(size_t)TT*BB*HH];     // per-dir highway projections
// h exchange, pre-split bf16: [parity][dir][b][k]
__device__ __nv_bfloat16 g_hh[2][2][BB*HH];
__device__ __nv_bfloat16 g_hl[2][2][BB*HH];
__device__ unsigned g_bar;

// bf16 split operands for projections
__device__ __nv_bfloat16 g_xh[(size_t)TT*BB*FF], g_xl[(size_t)TT*BB*FF];
__device__ __nv_bfloat16 g_yh[(size_t)TT*BB*FF], g_yl[(size_t)TT*BB*FF];
__device__ __nv_bfloat16 g_wxh[2*2*FF*GXN], g_wxl[2*2*FF*GXN];
__device__ __nv_bfloat16 g_wph[2*2*FF*HH],  g_wpl[2*2*FF*HH];

// ---------------- helpers ----------------------------------------------------
__device__ __forceinline__ void split1(float x, __nv_bfloat16& h, __nv_bfloat16& l) {
    h = __float2bfloat16(x);
    l = __float2bfloat16(x - __bfloat162float(h));
}

// transpose+split: features [b][t][512] fp32 -> xh/xl [t][b][512] bf16
__global__ void k_tin(const float* __restrict__ feat,
                      __nv_bfloat16* __restrict__ xh, __nv_bfloat16* __restrict__ xl) {
    int row = blockIdx.x;               // b*T + t
    int b = row >> 10, t = row & 1023;
    float4 v = ((const float4*)(feat + (size_t)row * FF))[threadIdx.x];
    size_t drow = ((size_t)t * BB + b) * FF + threadIdx.x * 4;
    __nv_bfloat16 h4[4], l4[4];
    split1(v.x, h4[0], l4[0]); split1(v.y, h4[1], l4[1]);
    split1(v.z, h4[2], l4[2]); split1(v.w, h4[3], l4[3]);
    *(uint2*)(xh + drow) = *(uint2*)h4;
    *(uint2*)(xl + drow) = *(uint2*)l4;
}

// generic fp32 -> bf16 hi/lo split (n4 = element count / 4)
__global__ void k_split(const float* __restrict__ in,
                        __nv_bfloat16* __restrict__ hi, __nv_bfloat16* __restrict__ lo, int n4) {
    int i = blockIdx.x * blockDim.x + threadIdx.x;
    if (i >= n4) return;
    float4 v = ((const float4*)in)[i];
    __nv_bfloat16 h4[4], l4[4];
    split1(v.x, h4[0], l4[0]); split1(v.y, h4[1], l4[1]);
    split1(v.z, h4[2], l4[2]); split1(v.w, h4[3], l4[3]);
    *(uint2*)(hi + (size_t)i * 4) = *(uint2*)h4;
    *(uint2*)(lo + (size_t)i * 4) = *(uint2*)l4;
}

// transpose: fin [t][b][512] -> out [b][t][512]
__global__ void k_tout(const float* __restrict__ fin, float* __restrict__ out) {
    int row = blockIdx.x;               // t*B + b
    int t = row >> 6, b = row & 63;
    const float4* s = (const float4*)(fin + (size_t)row * FF);
    float4* d = (float4*)(out + (((size_t)b << 10) + t) * FF);
    for (int i = threadIdx.x; i < FF / 4; i += blockDim.x) d[i] = s[i];
}

// ---------------- PTX wrappers -----------------------------------------------
__device__ __forceinline__ void ldsm_x4(uint32_t* r, uint32_t a) {
    asm volatile("ldmatrix.sync.aligned.m8n8.x4.shared.b16 {%0,%1,%2,%3}, [%4];"
        : "=r"(r[0]), "=r"(r[1]), "=r"(r[2]), "=r"(r[3]) : "r"(a));
}
__device__ __forceinline__ void ldsm_x4_t(uint32_t* r, uint32_t a) {
    asm volatile("ldmatrix.sync.aligned.m8n8.x4.trans.shared.b16 {%0,%1,%2,%3}, [%4];"
        : "=r"(r[0]), "=r"(r[1]), "=r"(r[2]), "=r"(r[3]) : "r"(a));
}
__device__ __forceinline__ void mma_bf16(float* c, const uint32_t* a, const uint32_t* b) {
    asm volatile("mma.sync.aligned.m16n8k16.row.col.f32.bf16.bf16.f32 "
        "{%0,%1,%2,%3},{%4,%5,%6,%7},{%8,%9},{%0,%1,%2,%3};"
        : "+f"(c[0]), "+f"(c[1]), "+f"(c[2]), "+f"(c[3])
        : "r"(a[0]), "r"(a[1]), "r"(a[2]), "r"(a[3]), "r"(b[0]), "r"(b[1]));
}
__device__ __forceinline__ void cp16(uint32_t s, const void* g) {
    asm volatile("cp.async.cg.shared.global [%0], [%1], 16;" :: "r"(s), "l"(g));
}
#define CP_COMMIT asm volatile("cp.async.commit_group;")
#define CP_WAIT1  asm volatile("cp.async.wait_group 1;")
#define CP_WAIT0  asm volatile("cp.async.wait_group 0;")

// ---------------- tensor-core split-bf16 GEMM (unchanged, proven) -------------
#define STG_A 10240               // 128 rows * 80B pitch
#define STG_B 8192                // 32 rows * 256B, XOR-swizzled
#define STG_SZ (2*STG_A + 2*STG_B)
#define SMEM_MMA (2*STG_SZ)       // double-buffered: 73728 B

__global__ __launch_bounds__(256)
void k_mma(const __nv_bfloat16* __restrict__ Ah, const __nv_bfloat16* __restrict__ Al,
           const __nv_bfloat16* __restrict__ Bh, const __nv_bfloat16* __restrict__ Bl,
           const float* __restrict__ bias, float* __restrict__ C, int N, int K) {
    extern __shared__ char smem[];
    uint32_t su = (uint32_t)__cvta_generic_to_shared(smem);
    int tid = threadIdx.x, lane = tid & 31, wid = tid >> 5;
    int mw = wid & 3, nw = wid >> 2;          // 4x2 warp grid
    int m0 = blockIdx.y * 128, n0 = blockIdx.x * 128;

    float acc[2][8][4];
#pragma unroll
    for (int mi = 0; mi < 2; mi++)
#pragma unroll
        for (int j = 0; j < 8; j++)
#pragma unroll
            for (int q = 0; q < 4; q++) acc[mi][j][q] = 0.f;

    auto load_stage = [&](int st, int k0) {
        uint32_t sa = su + st * STG_SZ;
#pragma unroll
        for (int hl = 0; hl < 2; hl++) {
            const __nv_bfloat16* Ap = hl ? Al : Ah;
            uint32_t sb = sa + hl * STG_A;
#pragma unroll
            for (int rep = 0; rep < 2; rep++) {
                int idx = tid + rep * 256;          // 0..511
                int r = idx >> 2, c = idx & 3;
                cp16(sb + r * 80 + c * 16, Ap + (size_t)(m0 + r) * K + k0 + c * 8);
            }
        }
#pragma unroll
        for (int hl = 0; hl < 2; hl++) {
            const __nv_bfloat16* Bp = hl ? Bl : Bh;
            uint32_t sb = sa + 2 * STG_A + hl * STG_B;
#pragma unroll
            for (int rep = 0; rep < 2; rep++) {
                int idx = tid + rep * 256;
                int k = idx >> 4, c = idx & 15;
                cp16(sb + k * 256 + ((c ^ (k & 7)) * 16),
                     Bp + (size_t)(k0 + k) * N + n0 + c * 8);
            }
        }
    };

    int NIT = K >> 5;                             // 16 for K=512
    load_stage(0, 0);
    CP_COMMIT;

    for (int it = 0; it < NIT; it++) {
        if (it + 1 < NIT) { load_stage((it + 1) & 1, (it + 1) * 32); CP_COMMIT; CP_WAIT1; }
        else              { CP_WAIT0; }
        __syncthreads();

        uint32_t sa = su + (it & 1) * STG_SZ;
#pragma unroll
        for (int kk = 0; kk < 2; kk++) {
            uint32_t ah[2][4], al[2][4];
            int arow_c = kk * 2 + (lane >> 4);
            int arow_r = (lane & 15);
#pragma unroll
            for (int mi = 0; mi < 2; mi++) {
                uint32_t ad = sa + (mw * 32 + mi * 16 + arow_r) * 80 + arow_c * 16;
                ldsm_x4(ah[mi], ad);
                ldsm_x4(al[mi], ad + STG_A);
            }
#pragma unroll
            for (int jp = 0; jp < 4; jp++) {
                int krow = kk * 16 + (lane & 15);
                int cch  = nw * 8 + jp * 2 + (lane >> 4);
                uint32_t bd = sa + 2 * STG_A + krow * 256 + ((cch ^ (krow & 7)) * 16);
                uint32_t bh[4], bl[4];
                ldsm_x4_t(bh, bd);
                ldsm_x4_t(bl, bd + STG_B);
#pragma unroll
                for (int jj = 0; jj < 2; jj++) {
#pragma unroll
                    for (int mi = 0; mi < 2; mi++) {
                        float* a4 = acc[mi][jp * 2 + jj];
                        mma_bf16(a4, ah[mi], &bh[jj * 2]);  // Ahi @ Bhi
                        mma_bf16(a4, ah[mi], &bl[jj * 2]);  // Ahi @ Blo
                        mma_bf16(a4, al[mi], &bh[jj * 2]);  // Alo @ Bhi
                    }
                }
            }
        }
        __syncthreads();
    }

#pragma unroll
    for (int mi = 0; mi < 2; mi++) {
#pragma unroll
        for (int j = 0; j < 8; j++) {
            int row = m0 + mw * 32 + mi * 16 + (lane >> 2);
            int col = n0 + nw * 64 + j * 8 + (lane & 3) * 2;
            float b0 = bias[col], b1 = bias[col + 1];
            float2 v0 = {acc[mi][j][0] + b0, acc[mi][j][1] + b1};
            float2 v1 = {acc[mi][j][2] + b0, acc[mi][j][3] + b1};
            *(float2*)(C + (size_t)row * N + col)       = v0;
            *(float2*)(C + (size_t)(row + 8) * N + col) = v1;
        }
    }
}

// ---------------- reset barrier + h buffers (before each recurrence) ---------
__global__ void k_reset() {
    int i = blockIdx.x * blockDim.x + threadIdx.x;   // 65536 threads
    if (i == 0) g_bar = 0u;
    if (i < 2 * 2 * BB * HH / 2) {        // 32768 u32 words per array
        ((uint32_t*)g_hh)[i] = 0u;
        ((uint32_t*)g_hl)[i] = 0u;
    }
}

// ---------------- persistent tensor-core bidirectional highway-LSTM scan -----
// grid = 128 blocks: blockIdx.x = d + 2*j  (d: direction, j: 4-col slice 0..63)
// block = 256 threads = 8 warps: warp = (m-tile mt = wid&3) x (k-half k2 = wid>>2)
// Per step:
//   1. stage pre-split h hi/lo (bf16, [b][k]) from L2 into smem (pitch 528)
//   2. mma m16n8k16 x 3 streams: z[64 b][20 n] = h @ Whslice  (n = gate*4+col)
//   3. k-half partials combined in smem; 256 gate threads (c=tid&3, b=tid>>2)
//      finish gates, write h hi/lo (split) back to L2 + fp32 out
//   4. grid barrier
// smem layout (bytes):
//   w_hi [256 k][80]   @ 0       (20480)   n-padded to 32, zeros beyond n=19
//   w_lo [256 k][80]   @ 20480   (20480)
//   h_hi [64 b][528]   @ 40960   (33792)
//   h_lo [64 b][528]   @ 74752   (33792)
//   z    [2 kh][64][24]@ 108544  (12288)
#define R_WHI 0
#define R_WLO 20480
#define R_HHI 40960
#define R_HLO 74752
#define R_Z   108544
#define REC_SMEM (R_Z + 2*64*24*4)   // 120832

__device__ __forceinline__ float sigf(float x) { return 1.f / (1.f + expf(-x)); }

__global__ __launch_bounds__(256, 1)
void k_rec(const float* __restrict__ Wh_l,   // [2][256][1280] (this layer)
           const float* __restrict__ bh_l,   // [2][1280]
           const float* __restrict__ gx0, const float* __restrict__ gx1,
           const float* __restrict__ px0, const float* __restrict__ px1,
           float* __restrict__ outbuf) {     // [t][b][512] (fwd|bwd concat)
    extern __shared__ char smc[];
    uint32_t su = (uint32_t)__cvta_generic_to_shared(smc);
    float* zbuf = (float*)(smc + R_Z);        // [2][64][24]

    int tid = threadIdx.x, lane = tid & 31, wid = tid >> 5;
    int d  = blockIdx.x & 1;
    int j  = blockIdx.x >> 1;
    int mt = wid & 3, k2 = wid >> 2;          // warp roles
    int c  = tid & 3, b = tid >> 2;           // gate-thread element (col c, batch b)
    int col = j * 4 + c;

    const float* Wh_d = Wh_l + (size_t)d * HH * GXN;
    const float* gx = d ? gx1 : gx0;
    const float* px = d ? px1 : px0;

    // fill Wh slice, split hi/lo: rows k (pitch 80B), cols n=gate*4+cc (20, pad->32 zeros)
    for (int idx = tid; idx < 256 * 32; idx += 256) {
        int k = idx >> 5, n = idx & 31;
        float v = 0.f;
        if (n < 20) v = Wh_d[(size_t)k * GXN + (n >> 2) * HH + j * 4 + (n & 3)];
        unsigned vb = __float_as_uint(v);
        unsigned short hib = (unsigned short)(vb >> 16);            // trunc split
        float lof = v - __uint_as_float(vb & 0xFFFF0000u);
        unsigned short lob;
        asm("cvt.rn.bf16.f32 %0, %1;" : "=h"(lob) : "f"(lof));
        ((unsigned short*)(smc + R_WHI + k * 80))[n] = hib;
        ((unsigned short*)(smc + R_WLO + k * 80))[n] = lob;
    }
    float bh5[5];
#pragma unroll
    for (int g = 0; g < 5; g++) bh5[g] = bh_l[(size_t)d * GXN + g * HH + col];

    float cs = 0.f;                  // cell state for (col, b)
    __syncthreads();

    for (int s = 0; s < TT; s++) {
        int t = d ? (TT - 1 - s) : s;

        // prefetch gate inputs for this thread's element (resolve during mma)
        size_t r0 = ((size_t)t * BB + b) * GXN;
        float gxa[5];
#pragma unroll
        for (int g = 0; g < 5; g++) gxa[g] = __ldg(gx + r0 + g * HH + col);
        float pxa = __ldg(px + ((size_t)t * BB + b) * HH + col);

        // stage h hi/lo from L2: thread (r=b, q=c) copies 128B of each stream.
        // chunk rotation i2=(i+2q)&7 makes the 528-pitch STS conflict-free.
        {
            int r = tid >> 2, q = tid & 3;
            const uint4* shi = (const uint4*)&g_hh[s & 1][d][0] + r * 32 + q * 8;
            const uint4* slo = (const uint4*)&g_hl[s & 1][d][0] + r * 32 + q * 8;
            char* dhi = smc + R_HHI + r * 528 + q * 128;
            char* dlo = smc + R_HLO + r * 528 + q * 128;
#pragma unroll
            for (int i = 0; i < 8; i++) {
                int i2 = (i + q * 2) & 7;
                *(uint4*)(dhi + i2 * 16) = __ldcg(shi + i2);
                *(uint4*)(dlo + i2 * 16) = __ldcg(slo + i2);
            }
        }
        __syncthreads();

        // mma: z[mt*16..+15 b][24 n] over k-half k2 (k = k2*128 .. +127)
        float acc[3][4];
#pragma unroll
        for (int nt = 0; nt < 3; nt++)
#pragma unroll
            for (int q = 0; q < 4; q++) acc[nt][q] = 0.f;

#pragma unroll
        for (int ks8 = 0; ks8 < 8; ks8++) {
            int ks = k2 * 8 + ks8;                // 16-k step index
            uint32_t ah[4], al[4];
            uint32_t aad = su + R_HHI + (mt * 16 + (lane & 15)) * 528
                         + ks * 32 + (lane >> 4) * 16;
            ldsm_x4(ah, aad);
            ldsm_x4(al, aad + (R_HLO - R_HHI));
            uint32_t brow = su + (ks * 16 + (lane & 15)) * 80;
            uint32_t bh0[4], bl0[4], bh1[4], bl1[4];
            ldsm_x4_t(bh0, brow + R_WHI + (0 + (lane >> 4)) * 16);
            ldsm_x4_t(bl0, brow + R_WLO + (0 + (lane >> 4)) * 16);
            ldsm_x4_t(bh1, brow + R_WHI + (2 + (lane >> 4)) * 16);
            ldsm_x4_t(bl1, brow + R_WLO + (2 + (lane >> 4)) * 16);
            // n-tiles: 0 -> bh0[0..1], 1 -> bh0[2..3], 2 -> bh1[0..1]
            mma_bf16(acc[0], ah, &bh0[0]); mma_bf16(acc[0], ah, &bl0[0]); mma_bf16(acc[0], al, &bh0[0]);
            mma_bf16(acc[1], ah, &bh0[2]); mma_bf16(acc[1], ah, &bl0[2]); mma_bf16(acc[1], al, &bh0[2]);
            mma_bf16(acc[2], ah, &bh1[0]); mma_bf16(acc[2], ah, &bl1[0]); mma_bf16(acc[2], al, &bh1[0]);
        }

        // store fragments to z[k2][batch][n]
        {
            float* zp = zbuf + k2 * (64 * 24);
            int row0 = mt * 16 + (lane >> 2);
            int col0 = (lane & 3) * 2;
#pragma unroll
            for (int nt = 0; nt < 3; nt++) {
                *(float2*)&zp[row0 * 24 + nt * 8 + col0]       = make_float2(acc[nt][0], acc[nt][1]);
                *(float2*)&zp[(row0 + 8) * 24 + nt * 8 + col0] = make_float2(acc[nt][2], acc[nt][3]);
            }
        }
        __syncthreads();

        // gates for element (col, b): z split order = i, o, f, u, r
        {
            float z5[5];
#pragma unroll
            for (int g = 0; g < 5; g++) {
                int n = g * 4 + c;
                z5[g] = zbuf[b * 24 + n] + zbuf[64 * 24 + b * 24 + n];
            }
            float zi = z5[0] + gxa[0] + bh5[0];
            float zo = z5[1] + gxa[1] + bh5[1];
            float zf = z5[2] + gxa[2] + bh5[2];
            float zu = z5[3] + gxa[3] + bh5[3];
            float zr = z5[4] + gxa[4] + bh5[4];
            cs = sigf(zi) * tanhf(zu) + sigf(zf) * cs;
            float hhv = sigf(zo) * tanhf(cs);
            float rg  = sigf(zr);
            float hf  = rg * hhv + (1.f - rg) * pxa;

            // split hf -> bf16 hi (trunc) + lo (rn of residual), write via L2
            unsigned fb = __float_as_uint(hf);
            unsigned short hib = (unsigned short)(fb >> 16);
            float lof = hf - __uint_as_float(fb & 0xFFFF0000u);
            unsigned short lob;
            asm("cvt.rn.bf16.f32 %0, %1;" : "=h"(lob) : "f"(lof));
            __nv_bfloat16* dh = &g_hh[(s + 1) & 1][d][b * HH + col];
            __nv_bfloat16* dl = &g_hl[(s + 1) & 1][d][b * HH + col];
            asm volatile("st.global.cg.u16 [%0], %1;" :: "l"(dh), "h"(hib) : "memory");
            asm volatile("st.global.cg.u16 [%0], %1;" :: "l"(dl), "h"(lob) : "memory");
            outbuf[((size_t)t * BB + b) * FF + d * HH + col] = hf;
        }

        // grid barrier: make h stores visible, arrive, spin on monotonic count
        __threadfence();
        __syncthreads();
        if (tid == 0) {
            atomicAdd(&g_bar, 1u);
            unsigned target = (unsigned)(s + 1) * NBLK;
            volatile unsigned* vb = &g_bar;
            while (*vb < target) __nanosleep(40);
        }
        __syncthreads();
    }
}

// ---------------------------- host driver ------------------------------------
extern "C" void kernel_launch(void* const* d_in, const int* in_sizes, int n_in,
                              void* d_out, int out_size) {
    (void)in_sizes; (void)n_in; (void)out_size;
    const float* feat = (const float*)d_in[0];
    const float* Wx   = (const float*)d_in[1];  // [2][2][512][1280]
    const float* bx   = (const float*)d_in[2];  // [2][2][1280]
    const float* Wh   = (const float*)d_in[3];  // [2][2][256][1280]
    const float* bh   = (const float*)d_in[4];  // [2][2][1280]
    const float* Wp   = (const float*)d_in[5];  // [2][2][512][256]
    const float* bp   = (const float*)d_in[6];  // [2][2][256]
    float* out = (float*)d_out;

    float *p_y, *p_f, *p_gx, *p_px;
    __nv_bfloat16 *p_xh, *p_xl, *p_yh, *p_yl, *p_wxh, *p_wxl, *p_wph, *p_wpl;
    cudaGetSymbolAddress((void**)&p_y,   g_y);
    cudaGetSymbolAddress((void**)&p_f,   g_fin);
    cudaGetSymbolAddress((void**)&p_gx,  g_gx);
    cudaGetSymbolAddress((void**)&p_px,  g_px);
    cudaGetSymbolAddress((void**)&p_xh,  g_xh);
    cudaGetSymbolAddress((void**)&p_xl,  g_xl);
    cudaGetSymbolAddress((void**)&p_yh,  g_yh);
    cudaGetSymbolAddress((void**)&p_yl,  g_yl);
    cudaGetSymbolAddress((void**)&p_wxh, g_wxh);
    cudaGetSymbolAddress((void**)&p_wxl, g_wxl);
    cudaGetSymbolAddress((void**)&p_wph, g_wph);
    cudaGetSymbolAddress((void**)&p_wpl, g_wpl);

    cudaFuncSetAttribute(k_rec, cudaFuncAttributeMaxDynamicSharedMemorySize, REC_SMEM);
    cudaFuncSetAttribute(k_mma, cudaFuncAttributeMaxDynamicSharedMemorySize, SMEM_MMA);

    const size_t GXSZ = (size_t)TT * BB * GXN;
    const size_t PXSZ = (size_t)TT * BB * HH;

    k_tin<<<TT * BB, 128>>>(feat, p_xh, p_xl);
    k_split<<<(2 * 2 * FF * GXN / 4 + 255) / 256, 256>>>(Wx, p_wxh, p_wxl, 2 * 2 * FF * GXN / 4);
    k_split<<<(2 * 2 * FF * HH  / 4 + 255) / 256, 256>>>(Wp, p_wph, p_wpl, 2 * 2 * FF * HH / 4);

    for (int l = 0; l < 2; l++) {
        const __nv_bfloat16* Ah = l ? p_yh : p_xh;
        const __nv_bfloat16* Al = l ? p_yl : p_xl;
        float* OUT = l ? p_f : p_y;
        for (int dd = 0; dd < 2; dd++) {
            int w = l * 2 + dd;
            k_mma<<<dim3(GXN / 128, (TT * BB) / 128), 256, SMEM_MMA>>>(
                Ah, Al, p_wxh + (size_t)w * FF * GXN, p_wxl + (size_t)w * FF * GXN,
                bx + (size_t)w * GXN, p_gx + dd * GXSZ, GXN, FF);
            k_mma<<<dim3(HH / 128, (TT * BB) / 128), 256, SMEM_MMA>>>(
                Ah, Al, p_wph + (size_t)w * FF * HH, p_wpl + (size_t)w * FF * HH,
                bp + (size_t)w * HH, p_px + dd * PXSZ, HH, FF);
        }
        k_reset<<<256, 256>>>();
        k_rec<<<NBLK, 256, REC_SMEM>>>(
            Wh + (size_t)l * 2 * HH * GXN, bh + (size_t)l * 2 * GXN,
            p_gx, p_gx + GXSZ, p_px, p_px + PXSZ, OUT);
        if (l == 0)
            k_split<<<(TT * BB * FF / 4) / 256, 256>>>(p_y, p_yh, p_yl, TT * BB * FF / 4);
    }

    k_tout<<<TT * BB, 128>>>(p_f, out);
}